// round 1
// baseline (speedup 1.0000x reference)
#include <cuda_runtime.h>
#include <math.h>

#define B 16
#define S 8192
#define C 256      // K_CH = D_MODEL
#define OUT 256
#define CHUNK 256
#define NCHUNK (S / CHUNK)   // 32

// ---------------- scratch (no allocations allowed) ----------------
__device__ float g_qk[B * C];          // Wk @ q  (per batch, per channel)
__device__ float g_bdot[B];            // q . bk
__device__ float g_m[B * NCHUNK];      // per-chunk max
__device__ float g_l[B * NCHUNK];      // per-chunk sumexp
__device__ float g_cv[B * NCHUNK * C]; // per-chunk weighted value sums
__device__ float g_ctx[B * OUT];       // final context row per batch

// ---------------- kernel 0: tiny preamble, one block -----------------
// q[b,o] = query[b,:] @ Wq[:,o] + bq[o]
// qk[b,c] = sum_o q[b,o] * Wk[c,o]
// bdot[b] = sum_o q[b,o] * bk[o]
__global__ void prep_kernel(const float* __restrict__ query,
                            const float* __restrict__ Wq,
                            const float* __restrict__ bq,
                            const float* __restrict__ Wk,
                            const float* __restrict__ bk) {
    __shared__ float q_sh[B][OUT];
    int t = threadIdx.x; // 0..255
    for (int b = 0; b < B; b++) {
        float acc = bq[t];
        const float* qrow = query + b * C;
        #pragma unroll 8
        for (int d = 0; d < C; d++)
            acc += qrow[d] * Wq[d * OUT + t];
        q_sh[b][t] = acc;
    }
    __syncthreads();
    for (int b = 0; b < B; b++) {
        float acc = 0.f;
        const float* wrow = Wk + t * OUT; // Wk row t (channel t)
        #pragma unroll 8
        for (int o = 0; o < OUT; o++)
            acc += q_sh[b][o] * wrow[o];
        g_qk[b * C + t] = acc;
    }
    if (t < B) {
        float acc = 0.f;
        #pragma unroll 8
        for (int o = 0; o < OUT; o++)
            acc += q_sh[t][o] * bk[o];
        g_bdot[t] = acc;
    }
}

// ---------------- kernel 1: fused key-scan + value-scan per chunk -----
// grid (NCHUNK, B), 256 threads
__global__ void attn_partial_kernel(const float* __restrict__ key,
                                    const float* __restrict__ value) {
    const int b = blockIdx.y;
    const int chunk = blockIdx.x;
    const int s0 = chunk * CHUNK;
    const int t = threadIdx.x;
    const int lane = t & 31;
    const int warp = t >> 5;

    __shared__ float qk_sh[C];
    __shared__ float p_sh[CHUNK];
    __shared__ float red[8];

    qk_sh[t] = g_qk[b * C + t];
    __syncthreads();

    const float bd = g_bdot[b];
    const float scale = 0.0625f; // 1/sqrt(256)
    const float4* qk4 = (const float4*)qk_sh;

    // ---- phase 1: scores for CHUNK rows; each warp handles rows warp, warp+8, ...
    for (int i = warp; i < CHUNK; i += 8) {
        const float4* krow = (const float4*)(key + ((size_t)b * S + s0 + i) * C);
        float acc = 0.f;
        #pragma unroll
        for (int j = 0; j < 2; j++) {
            float4 kv = krow[lane + 32 * j];
            float4 qv = qk4[lane + 32 * j];
            acc += kv.x * qv.x + kv.y * qv.y + kv.z * qv.z + kv.w * qv.w;
        }
        #pragma unroll
        for (int off = 16; off; off >>= 1)
            acc += __shfl_xor_sync(0xffffffffu, acc, off);
        if (lane == 0) p_sh[i] = (acc + bd) * scale;
    }
    __syncthreads();

    // ---- softmax partials over this chunk (block reduce max, sum)
    float sc = p_sh[t];
    float v = sc;
    #pragma unroll
    for (int off = 16; off; off >>= 1)
        v = fmaxf(v, __shfl_xor_sync(0xffffffffu, v, off));
    if (lane == 0) red[warp] = v;
    __syncthreads();
    float m = red[0];
    #pragma unroll
    for (int i = 1; i < 8; i++) m = fmaxf(m, red[i]);

    float p = __expf(sc - m);
    p_sh[t] = p;       // own index — no race; visibility after next sync
    __syncthreads();   // red reads done above; p_sh now visible everywhere

    float sv = p;
    #pragma unroll
    for (int off = 16; off; off >>= 1)
        sv += __shfl_xor_sync(0xffffffffu, sv, off);
    if (lane == 0) red[warp] = sv;
    __syncthreads();
    float l = red[0];
    #pragma unroll
    for (int i = 1; i < 8; i++) l += red[i];

    // ---- phase 2: cv[c=t] = sum_s p[s] * value[b, s0+s, t]  (coalesced column walk)
    const float* vbase = value + ((size_t)b * S + s0) * C + t;
    float acc0 = 0.f, acc1 = 0.f, acc2 = 0.f, acc3 = 0.f;
    #pragma unroll 4
    for (int s = 0; s < CHUNK; s += 4) {
        acc0 += p_sh[s + 0] * vbase[(size_t)(s + 0) * C];
        acc1 += p_sh[s + 1] * vbase[(size_t)(s + 1) * C];
        acc2 += p_sh[s + 2] * vbase[(size_t)(s + 2) * C];
        acc3 += p_sh[s + 3] * vbase[(size_t)(s + 3) * C];
    }
    float acc = (acc0 + acc1) + (acc2 + acc3);

    const int pidx = b * NCHUNK + chunk;
    g_cv[(size_t)pidx * C + t] = acc;
    if (t == 0) { g_m[pidx] = m; g_l[pidx] = l; }
}

// ---------------- kernel 2: combine partials + Wv projection ----------
// grid B, 256 threads
__global__ void combine_kernel(const float* __restrict__ Wv,
                               const float* __restrict__ bv) {
    const int b = blockIdx.x;
    const int t = threadIdx.x;

    // global max over chunks (redundant per-thread: 32 L2-hot loads)
    float gm = -INFINITY;
    #pragma unroll
    for (int i = 0; i < NCHUNK; i++)
        gm = fmaxf(gm, g_m[b * NCHUNK + i]);

    float gl = 0.f;
    float acc = 0.f;
    #pragma unroll 4
    for (int i = 0; i < NCHUNK; i++) {
        float w = __expf(g_m[b * NCHUNK + i] - gm);
        gl += g_l[b * NCHUNK + i] * w;
        acc += g_cv[(size_t)(b * NCHUNK + i) * C + t] * w;
    }
    float cx = acc / gl;

    __shared__ float cx_sh[C];
    cx_sh[t] = cx;
    __syncthreads();

    float o_acc = bv[t];
    #pragma unroll 8
    for (int c = 0; c < C; c++)
        o_acc += cx_sh[c] * Wv[c * OUT + t];
    g_ctx[b * OUT + t] = o_acc;
}

// ---------------- kernel 3: broadcast ctx row over S ------------------
// grid (S/64, B), 256 threads; each block writes 64 rows via float4
__global__ void bcast_kernel(float* __restrict__ out) {
    const int b = blockIdx.y;
    const int t = threadIdx.x;
    __shared__ float4 ctx4[OUT / 4]; // 64
    if (t < OUT / 4)
        ctx4[t] = ((const float4*)(g_ctx + b * OUT))[t];
    __syncthreads();

    const int row = t >> 6;   // 0..3
    const int col = t & 63;   // 0..63
    float4 val = ctx4[col];
    float4* o4 = (float4*)out;
    size_t base = ((size_t)b * S + (size_t)blockIdx.x * 64) * (C / 4);
    #pragma unroll
    for (int i = 0; i < 16; i++)
        o4[base + (size_t)(i * 4 + row) * (OUT / 4) + col] = val;
}

// ---------------- launch ------------------
extern "C" void kernel_launch(void* const* d_in, const int* in_sizes, int n_in,
                              void* d_out, int out_size) {
    const float* query = (const float*)d_in[0];
    const float* key   = (const float*)d_in[1];
    const float* value = (const float*)d_in[2];
    const float* Wq    = (const float*)d_in[3];
    const float* bq    = (const float*)d_in[4];
    const float* Wk    = (const float*)d_in[5];
    const float* bk    = (const float*)d_in[6];
    const float* Wv    = (const float*)d_in[7];
    const float* bv    = (const float*)d_in[8];
    float* out = (float*)d_out;

    prep_kernel<<<1, 256>>>(query, Wq, bq, Wk, bk);
    attn_partial_kernel<<<dim3(NCHUNK, B), 256>>>(key, value);
    combine_kernel<<<B, 256>>>(Wv, bv);
    bcast_kernel<<<dim3(S / 64, B), 256>>>(out);
}

// round 2
// speedup vs baseline: 6.3202x; 6.3202x over previous
#include <cuda_runtime.h>
#include <math.h>

#define B 16
#define S 8192
#define C 256      // K_CH = D_MODEL
#define OUT 256
#define SB 64            // rows per scores block
#define NSB (S / SB)     // 128 score partials per batch
#define VB 128           // rows per value block
#define NVB (S / VB)     // 64 value partials per batch

// ---------------- scratch (no allocations allowed) ----------------
__device__ float g_q[B * OUT];         // q = query @ Wq + bq
__device__ float g_qk[B * C];          // Wk @ q  (per batch, per channel)
__device__ float g_bdot[B];            // q . bk
__device__ float g_scores[B * S];      // raw scaled scores
__device__ float g_pm[B * NSB];        // per-block max
__device__ float g_pl[B * NSB];        // per-block sumexp
__device__ float g_gm[B];              // global max
__device__ float g_gli[B];             // 1 / global sumexp
__device__ float g_cv[B * NVB * C];    // per-block weighted value sums
__device__ float g_ctx[B * OUT];       // final context row per batch

// ---------------- kernel 1: q projection + bdot (grid B, 256 thr) ----
__global__ void prep_q_kernel(const float* __restrict__ query,
                              const float* __restrict__ Wq,
                              const float* __restrict__ bq,
                              const float* __restrict__ bk) {
    const int b = blockIdx.x;
    const int t = threadIdx.x;       // output index o
    const int lane = t & 31, warp = t >> 5;
    __shared__ float red[8];

    float acc = bq[t];
    const float* qrow = query + b * C;
    #pragma unroll 8
    for (int d = 0; d < C; d++)
        acc += qrow[d] * Wq[d * OUT + t];   // coalesced over t
    g_q[b * OUT + t] = acc;

    // bdot[b] = sum_o q[b,o] * bk[o]
    float v = acc * bk[t];
    #pragma unroll
    for (int off = 16; off; off >>= 1)
        v += __shfl_xor_sync(0xffffffffu, v, off);
    if (lane == 0) red[warp] = v;
    __syncthreads();
    if (t == 0) {
        float s = red[0];
        #pragma unroll
        for (int i = 1; i < 8; i++) s += red[i];
        g_bdot[b] = s;
    }
}

// ---------------- kernel 2: qk = Wk @ q (grid (B, C/8), 256 thr) -----
// one warp per output channel; coalesced float4 reads of Wk rows
__global__ void prep_qk_kernel(const float* __restrict__ Wk) {
    const int b = blockIdx.x;
    const int c = blockIdx.y * 8 + (threadIdx.x >> 5);
    const int lane = threadIdx.x & 31;
    __shared__ float q_sh[OUT];
    q_sh[threadIdx.x] = g_q[b * OUT + threadIdx.x];
    __syncthreads();

    const float4* w4 = (const float4*)(Wk + (size_t)c * OUT);
    const float4* q4 = (const float4*)q_sh;
    float acc = 0.f;
    #pragma unroll
    for (int j = 0; j < 2; j++) {
        float4 w = w4[lane + 32 * j];
        float4 q = q4[lane + 32 * j];
        acc += w.x * q.x + w.y * q.y + w.z * q.z + w.w * q.w;
    }
    #pragma unroll
    for (int off = 16; off; off >>= 1)
        acc += __shfl_xor_sync(0xffffffffu, acc, off);
    if (lane == 0) g_qk[b * C + c] = acc;
}

// ---------------- kernel 3: scores pass (grid (NSB, B), 256 thr) -----
// reads key once; each warp computes 8 rows, 2 at a time for MLP
__global__ void scores_kernel(const float* __restrict__ key) {
    const int b = blockIdx.y;
    const int s0 = blockIdx.x * SB;
    const int t = threadIdx.x, lane = t & 31, warp = t >> 5;

    __shared__ float qk_sh[C];
    __shared__ float sc_sh[SB];
    __shared__ float redm[2], redl[2];

    qk_sh[t] = g_qk[b * C + t];
    __syncthreads();

    const float bd = g_bdot[b];
    const float scale = 0.0625f;  // 1/sqrt(256)
    const float4* qk4 = (const float4*)qk_sh;

    #pragma unroll
    for (int i = 0; i < 8; i += 2) {
        const int r0 = warp * 8 + i;
        const float4* k0 = (const float4*)(key + ((size_t)b * S + s0 + r0) * C);
        const float4* k1 = (const float4*)(key + ((size_t)b * S + s0 + r0 + 1) * C);
        float a0 = 0.f, a1 = 0.f;
        #pragma unroll
        for (int j = 0; j < 2; j++) {
            float4 q = qk4[lane + 32 * j];
            float4 x = k0[lane + 32 * j];
            float4 y = k1[lane + 32 * j];
            a0 += x.x * q.x + x.y * q.y + x.z * q.z + x.w * q.w;
            a1 += y.x * q.x + y.y * q.y + y.z * q.z + y.w * q.w;
        }
        #pragma unroll
        for (int off = 16; off; off >>= 1) {
            a0 += __shfl_xor_sync(0xffffffffu, a0, off);
            a1 += __shfl_xor_sync(0xffffffffu, a1, off);
        }
        if (lane == 0) {
            sc_sh[r0]     = (a0 + bd) * scale;
            sc_sh[r0 + 1] = (a1 + bd) * scale;
        }
    }
    __syncthreads();

    // write raw scores + block-local softmax partials (threads 0..63)
    float sc = 0.f;
    if (t < SB) {
        sc = sc_sh[t];
        g_scores[(size_t)b * S + s0 + t] = sc;
        float v = sc;
        #pragma unroll
        for (int off = 16; off; off >>= 1)
            v = fmaxf(v, __shfl_xor_sync(0xffffffffu, v, off));
        if (lane == 0) redm[warp] = v;
    }
    __syncthreads();
    const float bm = fmaxf(redm[0], redm[1]);
    if (t < SB) {
        float p = __expf(sc - bm);
        #pragma unroll
        for (int off = 16; off; off >>= 1)
            p += __shfl_xor_sync(0xffffffffu, p, off);
        if (lane == 0) redl[warp] = p;
    }
    __syncthreads();
    if (t == 0) {
        g_pm[b * NSB + blockIdx.x] = bm;
        g_pl[b * NSB + blockIdx.x] = redl[0] + redl[1];
    }
}

// ---------------- kernel 4: softmax global reduce (grid B, 128 thr) --
__global__ void reduce_kernel() {
    const int b = blockIdx.x, t = threadIdx.x;  // 128 threads = NSB
    const int lane = t & 31, warp = t >> 5;
    __shared__ float sm[4], sl[4];

    const float pm = g_pm[b * NSB + t];
    const float pl = g_pl[b * NSB + t];

    float v = pm;
    #pragma unroll
    for (int off = 16; off; off >>= 1)
        v = fmaxf(v, __shfl_xor_sync(0xffffffffu, v, off));
    if (lane == 0) sm[warp] = v;
    __syncthreads();
    const float gm = fmaxf(fmaxf(sm[0], sm[1]), fmaxf(sm[2], sm[3]));

    float w = pl * __expf(pm - gm);
    #pragma unroll
    for (int off = 16; off; off >>= 1)
        w += __shfl_xor_sync(0xffffffffu, w, off);
    if (lane == 0) sl[warp] = w;
    __syncthreads();
    if (t == 0) {
        g_gm[b] = gm;
        g_gli[b] = 1.f / (sl[0] + sl[1] + sl[2] + sl[3]);
    }
}

// ---------------- kernel 5: value pass (grid (NVB, B), 256 thr) ------
// reads value once; thread t = channel, column walk with 4 accumulators
__global__ void vaccum_kernel(const float* __restrict__ value) {
    const int b = blockIdx.y;
    const int s0 = blockIdx.x * VB;
    const int t = threadIdx.x;
    __shared__ float w_sh[VB];

    const float gm = g_gm[b], gli = g_gli[b];
    if (t < VB)
        w_sh[t] = __expf(g_scores[(size_t)b * S + s0 + t] - gm) * gli;
    __syncthreads();

    const float* vb = value + ((size_t)b * S + s0) * C + t;
    float a0 = 0.f, a1 = 0.f, a2 = 0.f, a3 = 0.f;
    #pragma unroll 4
    for (int s = 0; s < VB; s += 4) {
        a0 += w_sh[s + 0] * vb[(size_t)(s + 0) * C];
        a1 += w_sh[s + 1] * vb[(size_t)(s + 1) * C];
        a2 += w_sh[s + 2] * vb[(size_t)(s + 2) * C];
        a3 += w_sh[s + 3] * vb[(size_t)(s + 3) * C];
    }
    g_cv[((size_t)(b * NVB + blockIdx.x)) * C + t] = (a0 + a1) + (a2 + a3);
}

// ---------------- kernel 6: combine + Wv projection (grid B, 256) ----
__global__ void project_kernel(const float* __restrict__ Wv,
                               const float* __restrict__ bv) {
    const int b = blockIdx.x, t = threadIdx.x;
    float acc = 0.f;
    #pragma unroll 8
    for (int i = 0; i < NVB; i++)
        acc += g_cv[((size_t)(b * NVB + i)) * C + t];  // coalesced over t

    __shared__ float cx_sh[C];
    cx_sh[t] = acc;
    __syncthreads();

    float o = bv[t];
    #pragma unroll 8
    for (int c = 0; c < C; c++)
        o += cx_sh[c] * Wv[c * OUT + t];               // coalesced over t
    g_ctx[b * OUT + t] = o;
}

// ---------------- kernel 7: broadcast ctx row over S -----------------
__global__ void bcast_kernel(float* __restrict__ out) {
    const int b = blockIdx.y;
    const int t = threadIdx.x;
    __shared__ float4 ctx4[OUT / 4];  // 64
    if (t < OUT / 4)
        ctx4[t] = ((const float4*)(g_ctx + b * OUT))[t];
    __syncthreads();

    const int row = t >> 6;   // 0..3
    const int col = t & 63;   // 0..63
    float4 val = ctx4[col];
    float4* o4 = (float4*)out;
    size_t base = ((size_t)b * S + (size_t)blockIdx.x * 64) * (C / 4);
    #pragma unroll
    for (int i = 0; i < 16; i++)
        o4[base + (size_t)(i * 4 + row) * (OUT / 4) + col] = val;
}

// ---------------- launch ------------------
extern "C" void kernel_launch(void* const* d_in, const int* in_sizes, int n_in,
                              void* d_out, int out_size) {
    const float* query = (const float*)d_in[0];
    const float* key   = (const float*)d_in[1];
    const float* value = (const float*)d_in[2];
    const float* Wq    = (const float*)d_in[3];
    const float* bq    = (const float*)d_in[4];
    const float* Wk    = (const float*)d_in[5];
    const float* bk    = (const float*)d_in[6];
    const float* Wv    = (const float*)d_in[7];
    const float* bv    = (const float*)d_in[8];
    float* out = (float*)d_out;

    prep_q_kernel<<<B, 256>>>(query, Wq, bq, bk);
    prep_qk_kernel<<<dim3(B, C / 8), 256>>>(Wk);
    scores_kernel<<<dim3(NSB, B), 256>>>(key);
    reduce_kernel<<<B, 128>>>();
    vaccum_kernel<<<dim3(NVB, B), 256>>>(value);
    project_kernel<<<B, 256>>>(Wv, bv);
    bcast_kernel<<<dim3(S / 64, B), 256>>>(out);
}